// round 16
// baseline (speedup 1.0000x reference)
#include <cuda_runtime.h>
#include <cuda_fp16.h>
#include <math.h>

// ===========================================================================
// RolloutModule via mma.sync m16n8k16 fp16 (fp32 accum), split precision
// hi*hi + lo*hi + hi*lo.  R13 design, resubmitted after infra failure:
// (1) B-tile bank-conflict swizzle (prior rounds had 4-way conflicts on
// every B ldmatrix); (2) CTA split into 2 independent 4-warp groups (M=64
// each) with private k16 stage pipelines and named barriers — no inter-group
// sync anywhere in the step loop, so one group's tensor bursts overlap the
// other group's epilogue/scalar bubbles.
// ===========================================================================

#define NT    256
#define AGC   128
#define CTAS  256
#define NSTEP 64

// smem byte offsets
#define SM_A    0          // A hi plane [128][256] fp16 = 65536
#define SM_ALO  65536      // A lo plane
#define SM_W1   131072     // W1 hi 8192 + lo 8192 (swizzled [256][16])
#define SM_WST  147456     // per-group: grp*32768 + buf*16384 (hi 8192, lo 8192)
#define SM_B1   212992
#define SM_B2   214016
#define SM_B3   215040
#define SM_WMU  216064     // wmu0[256], wmu1[256] f32
#define SM_PART 218112     // [grp][d][64][4] f32 = 4096
#define SM_BMU  222208
#define SM_TOT  222336

// Prepared weights: [layer][k16 stage][plane hi/lo][256n][16k], swizzled.
__device__ __align__(16) unsigned char g_w23[2][16][16384];
__device__ __align__(16) unsigned char g_w1[16384];

// ---------------------------------------------------------------------------
__device__ __forceinline__ unsigned smem_u32(const void* p) {
    unsigned a;
    asm("{ .reg .u64 t; cvta.to.shared.u64 t, %1; cvt.u32.u64 %0, t; }"
        : "=r"(a) : "l"(p));
    return a;
}
__device__ __forceinline__ void cp16(unsigned d, const void* s) {
    asm volatile("cp.async.cg.shared.global [%0], [%1], 16;" :: "r"(d), "l"(s));
}
__device__ __forceinline__ void cpcommit() { asm volatile("cp.async.commit_group;" ::: "memory"); }
template<int N> __device__ __forceinline__ void cpwait() {
    asm volatile("cp.async.wait_group %0;" :: "n"(N) : "memory");
}
__device__ __forceinline__ void gbar(int grp) {
    asm volatile("bar.sync %0, 128;" :: "r"(grp + 1) : "memory");
}

#define LDSM4(r0,r1,r2,r3,a) \
    asm volatile("ldmatrix.sync.aligned.m8n8.x4.shared.b16 {%0,%1,%2,%3}, [%4];" \
        : "=r"(r0),"=r"(r1),"=r"(r2),"=r"(r3) : "r"(a))

#define MMA(dd, a, b0, b1) \
    asm volatile("mma.sync.aligned.m16n8k16.row.col.f32.f16.f16.f32 " \
        "{%0,%1,%2,%3},{%4,%5,%6,%7},{%8,%9},{%0,%1,%2,%3};" \
        : "+f"((dd)[0]),"+f"((dd)[1]),"+f"((dd)[2]),"+f"((dd)[3]) \
        : "r"((a)[0]),"r"((a)[1]),"r"((a)[2]),"r"((a)[3]),"r"(b0),"r"(b1))

__device__ __forceinline__ float clampf(float v, float lo, float hi) {
    return fminf(fmaxf(v, lo), hi);
}

// A fragment (m16 x k16) from swizzled [128][256] fp16 plane (512B rows).
__device__ __forceinline__ void ldA(unsigned abase, int mbase, int k16,
                                    unsigned lane, unsigned* r) {
    int row = mbase + (int)(((lane >> 3) & 1) << 3) + (int)(lane & 7);
    int kc  = k16 * 2 + (int)(lane >> 4);
    unsigned addr = abase + (unsigned)(row * 512) +
                    ((unsigned)(kc ^ (row & 7)) << 4);
    LDSM4(r[0], r[1], r[2], r[3], addr);
}

// B n16 x k16 fragment from swizzled [256n][16k] plane (32B rows).
// physical chunk = logical chunk ^ ((nrow>>2)&1)  -> conflict-free phases.
__device__ __forceinline__ void ldB(unsigned wbase, int nbase,
                                    unsigned lane, unsigned* r) {
    int nrow = nbase + (int)((lane >> 4) << 3) + (int)(lane & 7);
    int kc   = (int)((lane >> 3) & 1) ^ ((nrow >> 2) & 1);
    unsigned addr = wbase + (unsigned)(nrow * 32) + ((unsigned)kc << 4);
    LDSM4(r[0], r[1], r[2], r[3], addr);
}

// One k16 step over warp tile 64m x 64n: 3-product split MMA, 96 MMAs.
__device__ __forceinline__ void kstep(float (*d)[8][4],
                                      unsigned ahib, unsigned alob, int k16,
                                      unsigned whib, unsigned wlob,
                                      int grp, int wn, unsigned lane)
{
    unsigned ah[4][4], al[4][4];
    #pragma unroll
    for (int mt = 0; mt < 4; ++mt) {
        ldA(ahib, grp * 64 + mt * 16, k16, lane, ah[mt]);
        ldA(alob, grp * 64 + mt * 16, k16, lane, al[mt]);
    }
    #pragma unroll
    for (int g = 0; g < 4; ++g) {
        unsigned bh4[4], bl4[4];
        ldB(whib, wn * 64 + g * 16, lane, bh4);
        ldB(wlob, wn * 64 + g * 16, lane, bl4);
        #pragma unroll
        for (int mt = 0; mt < 4; ++mt)
            #pragma unroll
            for (int q = 0; q < 2; ++q) {
                const int nt = g * 2 + q;
                MMA(d[mt][nt], ah[mt], bh4[q * 2], bh4[q * 2 + 1]);
                MMA(d[mt][nt], al[mt], bh4[q * 2], bh4[q * 2 + 1]);
                MMA(d[mt][nt], ah[mt], bl4[q * 2], bl4[q * 2 + 1]);
            }
    }
}

// Init accumulators with bias.
__device__ __forceinline__ void init_acc(float (*d)[8][4], const float* bias,
                                         int wn, int qn)
{
    float bb[8][2];
    #pragma unroll
    for (int nt = 0; nt < 8; ++nt) {
        const int n = wn * 64 + nt * 8 + qn;
        bb[nt][0] = bias[n]; bb[nt][1] = bias[n + 1];
    }
    #pragma unroll
    for (int mt = 0; mt < 4; ++mt)
        #pragma unroll
        for (int nt = 0; nt < 8; ++nt) {
            d[mt][nt][0] = bb[nt][0]; d[mt][nt][1] = bb[nt][1];
            d[mt][nt][2] = bb[nt][0]; d[mt][nt][3] = bb[nt][1];
        }
}

// Epilogue: relu (bias pre-added); STORE -> hi/lo planes; DOT -> output dots.
template<bool STORE, bool DOT>
__device__ __forceinline__ void epi(float (*d)[8][4],
                                    char* smem, const float* wmu0,
                                    const float* wmu1,
                                    int grp, int wn, unsigned lane)
{
    const int qrow = (int)(lane >> 2);
    const int qn   = (int)(lane & 3) * 2;
    float* partg = (float*)(smem + SM_PART) + grp * 512;
    #pragma unroll
    for (int mt = 0; mt < 4; ++mt) {
        const int m0 = mt * 16 + qrow;          // 0..63 within group
        const int m1 = m0 + 8;
        const int r0 = grp * 64 + m0;           // A-plane row
        const int r1 = r0 + 8;
        float s0a = 0.f, s1a = 0.f, s0b = 0.f, s1b = 0.f;
        #pragma unroll
        for (int nt = 0; nt < 8; ++nt) {
            const int n = wn * 64 + nt * 8 + qn;
            float v0 = fmaxf(d[mt][nt][0], 0.f);
            float v1 = fmaxf(d[mt][nt][1], 0.f);
            float v2 = fmaxf(d[mt][nt][2], 0.f);
            float v3 = fmaxf(d[mt][nt][3], 0.f);
            if (DOT) {
                s0a = fmaf(v0, wmu0[n], fmaf(v1, wmu0[n + 1], s0a));
                s1a = fmaf(v0, wmu1[n], fmaf(v1, wmu1[n + 1], s1a));
                s0b = fmaf(v2, wmu0[n], fmaf(v3, wmu0[n + 1], s0b));
                s1b = fmaf(v2, wmu1[n], fmaf(v3, wmu1[n + 1], s1b));
            }
            if (STORE) {
                const int chunk = n >> 3, off = (n & 7) * 2;
                __half2 hp0 = __float22half2_rn(make_float2(v0, v1));
                __half2 hp1 = __float22half2_rn(make_float2(v2, v3));
                __half2 lp0 = __float22half2_rn(make_float2(
                    v0 - __low2float(hp0), v1 - __high2float(hp0)));
                __half2 lp1 = __float22half2_rn(make_float2(
                    v2 - __low2float(hp1), v3 - __high2float(hp1)));
                const int p0 = r0 * 512 + ((chunk ^ (r0 & 7)) << 4) + off;
                const int p1 = r1 * 512 + ((chunk ^ (r1 & 7)) << 4) + off;
                *(__half2*)(smem + SM_A   + p0) = hp0;
                *(__half2*)(smem + SM_ALO + p0) = lp0;
                *(__half2*)(smem + SM_A   + p1) = hp1;
                *(__half2*)(smem + SM_ALO + p1) = lp1;
            }
        }
        if (DOT) {
            s0a += __shfl_xor_sync(0xffffffffu, s0a, 1);
            s0a += __shfl_xor_sync(0xffffffffu, s0a, 2);
            s1a += __shfl_xor_sync(0xffffffffu, s1a, 1);
            s1a += __shfl_xor_sync(0xffffffffu, s1a, 2);
            s0b += __shfl_xor_sync(0xffffffffu, s0b, 1);
            s0b += __shfl_xor_sync(0xffffffffu, s0b, 2);
            s1b += __shfl_xor_sync(0xffffffffu, s1b, 1);
            s1b += __shfl_xor_sync(0xffffffffu, s1b, 2);
            if ((lane & 3) == 0) {
                partg[m0 * 4 + wn]       = s0a;
                partg[256 + m0 * 4 + wn] = s1a;
                partg[m1 * 4 + wn]       = s0b;
                partg[256 + m1 * 4 + wn] = s1b;
            }
        }
    }
}

// Group copies one 16KB stage with its 128 threads (8 x cp16 each).
__device__ __forceinline__ void copy_stage(unsigned dstbuf,
                                           const unsigned char* src, int lt)
{
    #pragma unroll
    for (int i = 0; i < 8; ++i) {
        const unsigned off = (unsigned)((i * 128 + lt) * 16);
        cp16(dstbuf + off, src + off);
    }
    cpcommit();
}

// ---------------------------------------------------------------------------
// prep: split weights into fp16 hi/lo, transpose to [N][K], k16 stages,
// with bank-conflict swizzle: physical chunk = (kl>>3) ^ ((n>>2)&1).
// ---------------------------------------------------------------------------
__global__ void prep_kernel(const float* __restrict__ w1,
                            const float* __restrict__ w2,
                            const float* __restrict__ w3)
{
    int g = blockIdx.x * blockDim.x + threadIdx.x;
    if (g >= 270336) return;
    float x; unsigned char* dst; int plane, n, kl;
    if (g < 262144) {
        int layer = g >> 17;
        int r  = g & 131071;
        int s  = r >> 13;          // k16 stage 0..15
        int e  = r & 8191;
        plane  = e >> 12;
        int e2 = e & 4095;
        n = e2 >> 4; kl = e2 & 15;
        const float* w = layer ? w3 : w2;
        x = w[(s * 16 + kl) * 256 + n];
        dst = &g_w23[layer][s][plane * 8192];
    } else {
        int q = g - 262144;
        plane = q >> 12;
        int e = q & 4095;
        n = e >> 4; kl = e & 15;
        x = (kl < 13) ? w1[kl * 256 + n] : 0.f;
        dst = &g_w1[plane * 8192];
    }
    __half h = __float2half_rn(x);
    __half v = plane ? __float2half_rn(x - __half2float(h)) : h;
    const int off = n * 32 + (((kl >> 3) ^ ((n >> 2) & 1)) << 4) + (kl & 7) * 2;
    *reinterpret_cast<__half*>(dst + off) = v;
}

// ---------------------------------------------------------------------------
__global__ __launch_bounds__(NT, 1)
void rollout_tc(const float* __restrict__ pos0, const float* __restrict__ wind,
                const float* __restrict__ b1g, const float* __restrict__ b2g,
                const float* __restrict__ b3g,
                const float* __restrict__ wmug, const float* __restrict__ bmug,
                float* __restrict__ out)
{
    extern __shared__ char smem[];
    const unsigned sb = smem_u32(smem);
    const int t = threadIdx.x;
    const unsigned lane = (unsigned)(t & 31);
    const int warp = t >> 5;
    const int grp = warp >> 2;                 // 0/1: independent 4-warp group
    const int wn  = warp & 3;                  // n-quarter within group
    const int lt  = t & 127;                   // thread within group
    const int qn  = (int)(lane & 3) * 2;

    float* b1s  = (float*)(smem + SM_B1);
    float* b2s  = (float*)(smem + SM_B2);
    float* b3s  = (float*)(smem + SM_B3);
    float* wmu0 = (float*)(smem + SM_WMU);
    float* wmu1 = (float*)(smem + SM_WMU) + 256;
    float* bmus = (float*)(smem + SM_BMU);
    const unsigned stg = sb + SM_WST + (unsigned)(grp * 32768);

    // constants
    for (int i = t; i < 256; i += NT) {
        b1s[i] = b1g[i]; b2s[i] = b2g[i]; b3s[i] = b3g[i];
        wmu0[i] = wmug[2 * i]; wmu1[i] = wmug[2 * i + 1];
    }
    if (t < 2) bmus[t] = bmug[t];

    // resident W1 (CTA-wide, group 0), then per-group stage prologue (f0, f1)
    #pragma unroll
    for (int i = 0; i < 4; ++i) {
        const int off = (i * NT + t) * 16;
        cp16(sb + SM_W1 + off, g_w1 + off);
    }
    cpcommit();
    copy_stage(stg,         g_w23[0][0], lt);
    copy_stage(stg + 16384, g_w23[0][1], lt);
    cpwait<2>();           // W1 done; f0,f1 in flight
    __syncthreads();

    // agent state: thread lt<64 of group owns agent grp*64+lt
    const int gid = blockIdx.x * AGC + grp * 64 + lt;
    float px = 0.f, py = 0.f, wx = 0.f, wy = 0.f;
    float mxs = -INFINITY, ss = 0.f, mxr = -INFINITY, sr = 0.f;
    if (lt < 64) {
        px = pos0[gid * 2]; py = pos0[gid * 2 + 1];
        wx = wind[gid * 2]; wy = wind[gid * 2 + 1];
    }

    const unsigned ahib = sb + SM_A, alob = sb + SM_ALO;
    float d[4][8][4];

    #pragma unroll 1
    for (int step = 0; step < NSTEP; ++step) {
        // ---------------- observe -> A cols 0..15 (group rows) -----------
        if (lt < 64) {
            const int row = grp * 64 + lt;
            float obs[16];
            obs[0] = px * 0.1f;            obs[1] = py * 0.1f;
            obs[2] = (4.0f  - px) * 0.1f;  obs[3] = (3.0f  - py) * 0.1f;
            obs[4] = (1.75f - px) * 0.1f;  obs[5] = (1.75f - py) * 0.1f;
            obs[6] = (1.75f - px) * 0.1f;  obs[7] = (3.75f - py) * 0.1f;
            obs[8] = (3.75f - px) * 0.1f;  obs[9] = (2.0f  - py) * 0.1f;
            { float dx = px-1.75f, dy = py-1.75f; obs[10] = sqrtf(dx*dx+dy*dy+1e-9f) - 0.38f; }
            { float dx = px-1.75f, dy = py-3.75f; obs[11] = sqrtf(dx*dx+dy*dy+1e-9f) - 0.42f; }
            { float dx = px-3.75f, dy = py-2.0f;  obs[12] = sqrtf(dx*dx+dy*dy+1e-9f) - 0.34f; }
            obs[13] = 0.f; obs[14] = 0.f; obs[15] = 0.f;
            #pragma unroll
            for (int c = 0; c < 8; ++c) {
                const int k = c * 2;
                const int chunk = k >> 3, off = (k & 7) * 2;
                const int p = row * 512 + ((chunk ^ (row & 7)) << 4) + off;
                __half2 hp = __float22half2_rn(make_float2(obs[k], obs[k + 1]));
                *(__half2*)(smem + SM_A + p) = hp;
                *(__half2*)(smem + SM_ALO + p) = __float22half2_rn(make_float2(
                    obs[k]     - __low2float(hp),
                    obs[k + 1] - __high2float(hp)));
            }
        }
        gbar(grp);

        // ---------------- layer 1 (K=16, resident W1) --------------------
        init_acc(d, b1s, wn, qn);
        kstep(d, ahib, alob, 0, sb + SM_W1, sb + SM_W1 + 8192, grp, wn, lane);
        gbar(grp);                          // group done reading obs A
        epi<true, false>(d, smem, wmu0, wmu1, grp, wn, lane);
        gbar(grp);                          // A(l1) ready

        // ---------------- layers 2 & 3: 32 k16 stages, flat --------------
        int f = 0;
        #pragma unroll 1
        for (int l = 0; l < 2; ++l) {
            init_acc(d, l ? b3s : b2s, wn, qn);
            #pragma unroll 1
            for (int s = 0; s < 16; ++s) {
                cpwait<1>();                // own part of stage f landed
                gbar(grp);                  // whole group's part landed
                const unsigned wb = stg + (unsigned)((f & 1) * 16384);
                kstep(d, ahib, alob, s, wb, wb + 8192, grp, wn, lane);
                gbar(grp);                  // group done reading buffer
                const int f2 = (f + 2) & 31;
                copy_stage(wb, g_w23[f2 >> 4][f2 & 15], lt);
                ++f;
            }
            if (l == 0) {
                epi<true, false>(d, smem, wmu0, wmu1, grp, wn, lane);
                gbar(grp);                  // A(l2) ready
            } else {
                epi<false, true>(d, smem, wmu0, wmu1, grp, wn, lane);
                gbar(grp);                  // part[] ready
            }
        }

        // ---------------- combine output + integrate + margins -----------
        if (lt < 64) {
            const float* pg = (const float*)(smem + SM_PART) + grp * 512;
            float a0 = pg[lt*4] + pg[lt*4+1] + pg[lt*4+2] + pg[lt*4+3] + bmus[0];
            float a1 = pg[256 + lt*4] + pg[256 + lt*4+1]
                     + pg[256 + lt*4+2] + pg[256 + lt*4+3] + bmus[1];
            float ax = clampf(a0, -1.f, 1.f), ay = clampf(a1, -1.f, 1.f);
            float vx = 2.f * ax + wx, vy = 2.f * ay + wy;
            #pragma unroll
            for (int s_ = 0; s_ < 4; ++s_) {
                px = clampf(px + 0.0625f * vx, -4.f, 10.f);
                py = clampf(py + 0.0625f * vy, -4.f, 10.f);
            }
            float d0x = px-1.75f, d0y = py-1.75f;
            float c0 = sqrtf(d0x*d0x + d0y*d0y + 1e-9f) - 0.38f;
            float d1x = px-1.75f, d1y = py-3.75f;
            float c1 = sqrtf(d1x*d1x + d1y*d1y + 1e-9f) - 0.42f;
            float d2x = px-3.75f, d2y = py-2.0f;
            float c2 = sqrtf(d2x*d2x + d2y*d2y + 1e-9f) - 0.34f;
            float x0 = -50.f*c0, x1 = -50.f*c1, x2 = -50.f*c2;
            float mM = fmaxf(x0, fmaxf(x1, x2));
            float safe = -(mM + logf(expf(x0-mM) + expf(x1-mM) + expf(x2-mM))) * 0.02f;
            float xs = -8.f * safe;
            if (xs > mxs) { ss = ss * expf(mxs - xs) + 1.f; mxs = xs; }
            else          { ss += expf(xs - mxs); }
            float gx = px - 4.f, gy = py - 3.f;
            float gdist = sqrtf(gx*gx + gy*gy + 1e-9f);
            float xr = 8.f * (0.45f - gdist);
            if (xr > mxr) { sr = sr * expf(mxr - xr) + 1.f; mxr = xr; }
            else          { sr += expf(xr - mxr); }
        }
        // no trailing barrier needed: next obs is written by the same
        // threads; other group warps wait at the obs gbar.
    }

    cpwait<0>();   // drain trailing prefetches
    if (lt < 64) {
        float rho_safe  = -(mxs + logf(ss)) * 0.125f;
        float rho_reach =  (mxr + logf(sr)) * 0.125f;
        float xa = -8.f * rho_safe, xb = -8.f * rho_reach;
        float mm = fmaxf(xa, xb);
        out[gid] = -(mm + logf(expf(xa - mm) + expf(xb - mm))) * 0.125f;
    }
}

// ---------------------------------------------------------------------------
extern "C" void kernel_launch(void* const* d_in, const int* in_sizes, int n_in,
                              void* d_out, int out_size)
{
    (void)in_sizes; (void)n_in; (void)out_size;
    const float* pos0 = (const float*)d_in[0];
    const float* wind = (const float*)d_in[1];
    const float* w1   = (const float*)d_in[2];
    const float* b1   = (const float*)d_in[3];
    const float* w2   = (const float*)d_in[4];
    const float* b2   = (const float*)d_in[5];
    const float* w3   = (const float*)d_in[6];
    const float* b3   = (const float*)d_in[7];
    const float* wmu  = (const float*)d_in[8];
    const float* bmu  = (const float*)d_in[9];
    float* out = (float*)d_out;

    prep_kernel<<<(270336 + 255) / 256, 256>>>(w1, w2, w3);

    cudaFuncSetAttribute(rollout_tc,
                         cudaFuncAttributeMaxDynamicSharedMemorySize, SM_TOT);
    rollout_tc<<<CTAS, NT, SM_TOT>>>(pos0, wind, b1, b2, b3, wmu, bmu, out);
}